// round 8
// baseline (speedup 1.0000x reference)
#include <cuda_runtime.h>
#include <math.h>
#include <float.h>

#define B 4
#define T 8
#define NF 8192
#define C 384
#define H 12
#define TOPK 32
#define D 32
#define HT (H*T)        /* 96 */
#define ROWS (T+NF)     /* 8200 */
#define NH (NF/2)       /* 4096 per stage-1 half */
#define SCALE 0.17677669529663687f

typedef unsigned long long ull;
typedef unsigned int uint;

// ---------------- scratch (static device globals; no runtime alloc) ----------
__device__ float g_qk[B*HT*C];
__device__ float g_attn[(size_t)B*HT*NF];         // ~12.6MB
__device__ float g_w[B*HT*TOPK];
__device__ int   g_idx[B*HT*TOPK];
__device__ float g_fb[B*T*H*C];
__device__ ull   g_cand[B*HT][2][TOPK];           // stage-1 sorted candidates

// ---------------- helpers -----------------------------------------------------
__device__ __forceinline__ void red_add_v4(float* p, float4 v) {
    asm volatile("red.global.add.v4.f32 [%0], {%1, %2, %3, %4};"
                 :: "l"(p), "f"(v.x), "f"(v.y), "f"(v.z), "f"(v.w) : "memory");
}
__device__ __forceinline__ uint to_tf32(float f) {
    uint r;
    asm("cvt.rna.tf32.f32 %0, %1;" : "=r"(r) : "f"(f));
    return r;
}
__device__ __forceinline__ void mma_tf32(float* d,
                                         uint a0, uint a1, uint a2, uint a3,
                                         uint b0, uint b1) {
    asm("mma.sync.aligned.m16n8k8.row.col.f32.tf32.tf32.f32 "
        "{%0,%1,%2,%3}, {%4,%5,%6,%7}, {%8,%9}, {%0,%1,%2,%3};"
        : "+f"(d[0]), "+f"(d[1]), "+f"(d[2]), "+f"(d[3])
        : "r"(a0), "r"(a1), "r"(a2), "r"(a3), "r"(b0), "r"(b1));
}

// ---------------- kernel 1: zero the output (split for launch alignment) -----
__global__ void zero_out_kernel(float4* __restrict__ out, int n4) {
    float4 z = make_float4(0.f, 0.f, 0.f, 0.f);
    for (int i = blockIdx.x * blockDim.x + threadIdx.x; i < n4;
         i += gridDim.x * blockDim.x)
        out[i] = z;
}

// ---------------- kernel 2: fused q projection + qk fold ---------------------
__global__ __launch_bounds__(384) void qqk_kernel(const float* __restrict__ x,
                                                  const float* __restrict__ qs_w,
                                                  const float* __restrict__ kv_w) {
    int b = blockIdx.y, t = blockIdx.x;
    int tid = threadIdx.x;                 // 384
    __shared__ float xs[C];
    __shared__ float qs[C];
    xs[tid] = x[((size_t)b*ROWS + t)*C + tid];
    __syncthreads();

    float a0 = 0.f, a1 = 0.f, a2 = 0.f, a3 = 0.f;
    const float* w = qs_w + (size_t)t*C*C + tid;
    #pragma unroll 4
    for (int c = 0; c < C; c += 4) {
        a0 += xs[c    ] * w[(size_t)(c    )*C];
        a1 += xs[c + 1] * w[(size_t)(c + 1)*C];
        a2 += xs[c + 2] * w[(size_t)(c + 2)*C];
        a3 += xs[c + 3] * w[(size_t)(c + 3)*C];
    }
    qs[tid] = (a0 + a1) + (a2 + a3);
    __syncthreads();

    const float4* kvr = (const float4*)(kv_w + (size_t)tid*(2*C));
    #pragma unroll
    for (int h = 0; h < H; h++) {
        float s = 0.f;
        #pragma unroll
        for (int d4 = 0; d4 < 8; d4++) {
            float4 kq = kvr[h*8 + d4];
            s += qs[h*D + 4*d4 + 0]*kq.x + qs[h*D + 4*d4 + 1]*kq.y
               + qs[h*D + 4*d4 + 2]*kq.z + qs[h*D + 4*d4 + 3]*kq.w;
        }
        g_qk[(((size_t)b*H + h)*T + t)*C + tid] = s * SCALE;
    }
}

// ---------------- kernel 3: attn GEMM, 3xTF32, warp tile 48x64 ---------------
// Block 96x128, 128 threads = 4 warps (2m x 2n). Packed-fragment smem layout:
// each 16B group = {hi_k, lo_k, hi_{k+4}, lo_{k+4}} -> one LDS.128 per frag pair.
// Row stride 80 floats ( == 16 mod 32 banks) -> conflict-free LDS.128 phases.
#define ASTRIDE 80
#define A_FLOATS (96*ASTRIDE)
#define B_FLOATS (128*ASTRIDE)
#define GEMM_SMEM_BYTES ((A_FLOATS + B_FLOATS) * 4)

__global__ __launch_bounds__(128, 3) void attn_gemm_kernel(const float* __restrict__ x) {
    extern __shared__ __align__(16) float smem_f[];
    float* sA = smem_f;                    // [96][80]
    float* sB = smem_f + A_FLOATS;         // [128][80]

    int b  = blockIdx.y;
    int n0 = blockIdx.x * 128;
    int tid = threadIdx.x;
    int wid = tid >> 5, lane = tid & 31;
    int g = lane >> 2, tig = lane & 3;
    int wm = wid & 1, wn = wid >> 1;       // 2x2 warp grid

    const float* qk   = g_qk + (size_t)b*HT*C;
    const float* feat = x + ((size_t)b*ROWS + T)*C;

    float acc[3][8][4];
    #pragma unroll
    for (int i = 0; i < 3; i++)
        #pragma unroll
        for (int j = 0; j < 8; j++)
            #pragma unroll
            for (int r = 0; r < 4; r++) acc[i][j][r] = 0.f;

    #pragma unroll 1
    for (int chunk = 0; chunk < 12; chunk++) {
        int c0 = chunk * 32;
        __syncthreads();
        // stage A (96x32): hi/lo split into packed layout
        #pragma unroll
        for (int j = 0; j < 24; j++) {
            int idx = tid + j*128;
            int m = idx >> 5, k = idx & 31;
            float a = qk[(size_t)m*C + c0 + k];
            float hf = __uint_as_float(to_tf32(a));
            float lf = __uint_as_float(to_tf32(a - hf));
            int off = m*ASTRIDE + (k >> 3)*16 + (k & 3)*4 + ((k >> 2) & 1)*2;
            *(float2*)&sA[off] = make_float2(hf, lf);
        }
        // stage B (128x32)
        #pragma unroll
        for (int j = 0; j < 32; j++) {
            int idx = tid + j*128;
            int n = idx >> 5, k = idx & 31;
            float v = feat[(size_t)(n0 + n)*C + c0 + k];
            float hf = __uint_as_float(to_tf32(v));
            float lf = __uint_as_float(to_tf32(v - hf));
            int off = n*ASTRIDE + (k >> 3)*16 + (k & 3)*4 + ((k >> 2) & 1)*2;
            *(float2*)&sB[off] = make_float2(hf, lf);
        }
        __syncthreads();

        #pragma unroll
        for (int k8 = 0; k8 < 4; k8++) {
            int koff = k8*16 + tig*4;
            float4 bf[8];
            #pragma unroll
            for (int nt = 0; nt < 8; nt++)
                bf[nt] = *(const float4*)&sB[(wn*64 + nt*8 + g)*ASTRIDE + koff];
            #pragma unroll
            for (int mt = 0; mt < 3; mt++) {
                int m0 = wm*48 + mt*16;
                float4 a0 = *(const float4*)&sA[(m0 + g    )*ASTRIDE + koff];
                float4 a1 = *(const float4*)&sA[(m0 + g + 8)*ASTRIDE + koff];
                uint ah0 = __float_as_uint(a0.x), ah1 = __float_as_uint(a1.x);
                uint ah2 = __float_as_uint(a0.z), ah3 = __float_as_uint(a1.z);
                uint al0 = __float_as_uint(a0.y), al1 = __float_as_uint(a1.y);
                uint al2 = __float_as_uint(a0.w), al3 = __float_as_uint(a1.w);
                #pragma unroll
                for (int nt = 0; nt < 8; nt++) {
                    uint bh0 = __float_as_uint(bf[nt].x);
                    uint bh1 = __float_as_uint(bf[nt].z);
                    uint bl0 = __float_as_uint(bf[nt].y);
                    uint bl1 = __float_as_uint(bf[nt].w);
                    float* d = acc[mt][nt];
                    mma_tf32(d, ah0, ah1, ah2, ah3, bh0, bh1);
                    mma_tf32(d, ah0, ah1, ah2, ah3, bl0, bl1);
                    mma_tf32(d, al0, al1, al2, al3, bh0, bh1);
                }
            }
        }
    }

    float* outp = g_attn + (size_t)b*HT*NF;
    #pragma unroll
    for (int mt = 0; mt < 3; mt++) {
        int m0 = wm*48 + mt*16;
        #pragma unroll
        for (int nt = 0; nt < 8; nt++) {
            int nc = n0 + wn*64 + nt*8 + 2*tig;
            *(float2*)&outp[(size_t)(m0 + g    )*NF + nc] =
                make_float2(acc[mt][nt][0], acc[mt][nt][1]);
            *(float2*)&outp[(size_t)(m0 + g + 8)*NF + nc] =
                make_float2(acc[mt][nt][2], acc[mt][nt][3]);
        }
    }
}

// ---------------- top-k stage 1: exact top-32 per 4096-half -------------------
__device__ __forceinline__ unsigned enc_key(unsigned b) {
    return (b & 0x80000000u) ? ~b : (b | 0x80000000u);
}
__device__ __forceinline__ float dec_key(unsigned u) {
    unsigned b = (u & 0x80000000u) ? (u ^ 0x80000000u) : ~u;
    return __uint_as_float(b);
}

__global__ __launch_bounds__(256) void topk_stage1_kernel() {
    int blk  = blockIdx.x;                 // row*2 + half
    int row  = blk >> 1;
    int half = blk & 1;
    int base = half * NH;
    int tid = threadIdx.x;                 // 256
    int lane = tid & 31, wp = tid >> 5;
    __shared__ unsigned keys[NH];          // 16KB
    __shared__ unsigned hist[256];
    __shared__ unsigned wsuf[8];
    __shared__ unsigned sh_need, sh_prefix;
    __shared__ int cntG;
    __shared__ unsigned candK[TOPK];
    __shared__ int candI[TOPK];
    __shared__ int ri[256];

    hist[tid] = 0;
    if (tid == 0) { sh_need = TOPK; sh_prefix = 0; cntG = 0; }
    __syncthreads();

    const uint4* src = (const uint4*)(g_attn + (size_t)row*NF + base);
    for (int i = tid; i < NH/4; i += 256) {
        uint4 u = src[i];
        unsigned k0 = enc_key(u.x), k1 = enc_key(u.y);
        unsigned k2 = enc_key(u.z), k3 = enc_key(u.w);
        keys[4*i+0] = k0; keys[4*i+1] = k1;
        keys[4*i+2] = k2; keys[4*i+3] = k3;
        atomicAdd(&hist[k0 >> 24], 1u);
        atomicAdd(&hist[k1 >> 24], 1u);
        atomicAdd(&hist[k2 >> 24], 1u);
        atomicAdd(&hist[k3 >> 24], 1u);
    }
    __syncthreads();

    #pragma unroll
    for (int pass = 0; pass < 4; pass++) {
        int shift = 24 - 8*pass;
        if (pass > 0) {
            hist[tid] = 0;
            __syncthreads();
            unsigned pref  = sh_prefix;
            unsigned pmask = 0xFFFFFFFFu << (shift + 8);
            for (int i = tid; i < NH; i += 256) {
                unsigned k = keys[i];
                if ((k & pmask) == pref) atomicAdd(&hist[(k >> shift) & 255], 1u);
            }
            __syncthreads();
        }

        unsigned v = hist[tid];
        unsigned inc = v;
        #pragma unroll
        for (int s = 1; s < 32; s <<= 1) {
            unsigned tv = __shfl_down_sync(0xffffffffu, inc, s);
            if (lane + s < 32) inc += tv;
        }
        if (lane == 0) wsuf[wp] = inc;
        __syncthreads();
        if (tid < 8) {
            unsigned tv = wsuf[tid];
            #pragma unroll
            for (int s = 1; s < 8; s <<= 1) {
                unsigned t2 = __shfl_down_sync(0xffu, tv, s);
                if (tid + s < 8) tv += t2;
            }
            wsuf[tid] = tv;
        }
        __syncthreads();
        unsigned incl = inc + (wp < 7 ? wsuf[wp + 1] : 0u);
        unsigned need = sh_need;
        unsigned excl = incl - v;
        if (incl >= need && excl < need) {
            sh_prefix = sh_prefix | ((unsigned)tid << shift);
            sh_need   = need - excl;
        }
        __syncthreads();
    }
    unsigned V = sh_prefix;
    int E = (int)sh_need;

    for (int i = tid; i < NH; i += 256) {
        unsigned k = keys[i];
        if (k > V) { int p = atomicAdd(&cntG, 1); candK[p] = k; candI[p] = base + i; }
    }
    __syncthreads();
    int G = cntG;

    int last = -1;
    for (int e = 0; e < E; e++) {
        int best = NH;
        for (int i = tid; i < NH; i += 256)
            if (keys[i] == V && i > last && i < best) best = i;
        ri[tid] = best;
        __syncthreads();
        for (int s = 128; s > 0; s >>= 1) {
            if (tid < s) ri[tid] = min(ri[tid], ri[tid + s]);
            __syncthreads();
        }
        int widx = ri[0];
        if (tid == 0) { candK[G + e] = V; candI[G + e] = base + widx; }
        last = widx;
        __syncthreads();
    }

    if (tid < 32) {
        unsigned k = candK[tid];
        int ix = candI[tid];
        ull ck = ((ull)k << 32) | (ull)(0xFFFFFFFFu - (unsigned)ix);
        int rank = 0;
        #pragma unroll
        for (int j = 0; j < 32; j++) {
            ull o = __shfl_sync(0xffffffffu, ck, j);
            rank += (o > ck);
        }
        g_cand[row][half][rank] = ck;
    }
}

// ---------------- top-k stage 2: merge halves + softmax -----------------------
__global__ __launch_bounds__(128) void topk_merge_kernel() {
    int row  = blockIdx.x * 4 + (threadIdx.x >> 5);
    int lane = threadIdx.x & 31;

    ull a = g_cand[row][0][lane];
    ull bq = g_cand[row][1][31 - lane];
    ull c = a > bq ? a : bq;

    #pragma unroll
    for (int st = 16; st > 0; st >>= 1) {
        ull o = __shfl_xor_sync(0xffffffffu, c, st);
        bool up = (lane & st) == 0;
        c = up ? (c > o ? c : o) : (c < o ? c : o);
    }

    float val = dec_key((unsigned)(c >> 32));
    int   idx = (int)(0xFFFFFFFFu - (unsigned)(c & 0xFFFFFFFFu));

    float m = __shfl_sync(0xffffffffu, val, 0);
    float e = expf(val - m);
    float sum = e;
    #pragma unroll
    for (int o = 16; o > 0; o >>= 1) sum += __shfl_xor_sync(0xffffffffu, sum, o);

    g_w[row*TOPK + lane]   = e / sum;
    g_idx[row*TOPK + lane] = idx;
}

// ---------------- kernel 5: fused gather (fb) + vectorized sparse scatter ----
__global__ __launch_bounds__(384) void gather_scatter_kernel(const float* __restrict__ x,
                                                             const float* __restrict__ experts_w,
                                                             float* __restrict__ out) {
    int t = blockIdx.x, h = blockIdx.y, b = blockIdx.z;
    int tid = threadIdx.x;                 // 384
    __shared__ float wsh[TOPK];
    __shared__ int   ish[TOPK];
    __shared__ float fsh[TOPK][D];
    __shared__ __align__(16) float sc[4][C];

    int row = (b*H + h)*T + t;
    if (tid < TOPK) {
        wsh[tid] = g_w[row*TOPK + tid];
        ish[tid] = g_idx[row*TOPK + tid];
    }
    __syncthreads();

    const float* feat = x + ((size_t)b*ROWS + T)*C;
    int c = tid;
    int hD = h*D;
    bool mine = (c >= hD) && (c < hD + D);
    int d = c - hD;
    float a = 0.f;
    #pragma unroll
    for (int k = 0; k < TOPK; k++) {
        float v  = feat[(size_t)ish[k]*C + c];
        float wv = wsh[k] * v;
        a += wv;
        if (mine) fsh[k][d] = wv;
    }
    g_fb[(((size_t)b*T + t)*H + h)*C + c] = a;
    __syncthreads();

    int o = tid;
    float ecol[D];
    const float* ew = experts_w + ((size_t)t*C + hD)*C + o;
    #pragma unroll
    for (int d2 = 0; d2 < D; d2++) ecol[d2] = ew[(size_t)d2*C];

    float* outb = out + ((size_t)b*ROWS + T)*C;
    int kq = tid / (C/4);
    int o4 = tid % (C/4);
    #pragma unroll 1
    for (int gI = 0; gI < TOPK/4; gI++) {
        #pragma unroll
        for (int j = 0; j < 4; j++) {
            int k = gI*4 + j;
            float s = 0.f;
            #pragma unroll
            for (int d2 = 0; d2 < D; d2++) s += fsh[k][d2] * ecol[d2];
            sc[j][o] = s;
        }
        __syncthreads();
        float4 v = *(const float4*)&sc[kq][4*o4];
        red_add_v4(&outb[(size_t)ish[gI*4 + kq]*C + 4*o4], v);
        __syncthreads();
    }
}

// ---------------- kernel 6: attn_token projection + token_out ----------------
__global__ __launch_bounds__(384) void token_out_kernel(const float* __restrict__ kv_w,
                                                        const float* __restrict__ experts_w,
                                                        float* __restrict__ out) {
    int b = blockIdx.y, t = blockIdx.x;
    int tid = threadIdx.x;                 // 384
    __shared__ float fb[H*C];              // 18KB
    __shared__ float at[C];

    const float* fbg = g_fb + ((size_t)b*T + t)*H*C;
    for (int i = tid; i < H*C; i += 384) fb[i] = fbg[i];
    __syncthreads();

    {
        int h = tid >> 5, d = tid & 31;
        const float* col = kv_w + C + h*D + d;
        float a0 = 0.f, a1 = 0.f, a2 = 0.f, a3 = 0.f;
        #pragma unroll 2
        for (int c = 0; c < C; c += 4) {
            a0 += fb[h*C + c    ] * col[(size_t)(c    )*(2*C)];
            a1 += fb[h*C + c + 1] * col[(size_t)(c + 1)*(2*C)];
            a2 += fb[h*C + c + 2] * col[(size_t)(c + 2)*(2*C)];
            a3 += fb[h*C + c + 3] * col[(size_t)(c + 3)*(2*C)];
        }
        at[h*D + d] = (a0 + a1) + (a2 + a3);
    }
    __syncthreads();
    {
        const float* ew = experts_w + (size_t)t*C*C + tid;
        float a0 = 0.f, a1 = 0.f, a2 = 0.f, a3 = 0.f;
        #pragma unroll 2
        for (int c = 0; c < C; c += 4) {
            a0 += at[c    ] * ew[(size_t)(c    )*C];
            a1 += at[c + 1] * ew[(size_t)(c + 1)*C];
            a2 += at[c + 2] * ew[(size_t)(c + 2)*C];
            a3 += at[c + 3] * ew[(size_t)(c + 3)*C];
        }
        out[((size_t)b*ROWS + t)*C + tid] = (a0 + a1) + (a2 + a3);
    }
}

// ---------------- launcher ----------------------------------------------------
extern "C" void kernel_launch(void* const* d_in, const int* in_sizes, int n_in,
                              void* d_out, int out_size) {
    const float* x = nullptr; const float* qs_w = nullptr;
    const float* kv_w = nullptr; const float* experts_w = nullptr;
    for (int i = 0; i < n_in; i++) {
        if (in_sizes[i] == B*ROWS*C)      x = (const float*)d_in[i];
        else if (in_sizes[i] == C*2*C)    kv_w = (const float*)d_in[i];
        else if (in_sizes[i] == T*C*C) {
            if (!qs_w) qs_w = (const float*)d_in[i];
            else       experts_w = (const float*)d_in[i];
        }
    }
    float* out = (float*)d_out;

    cudaFuncSetAttribute(attn_gemm_kernel,
                         cudaFuncAttributeMaxDynamicSharedMemorySize,
                         (int)GEMM_SMEM_BYTES);

    int n4 = out_size / 4;
    int h4 = n4 / 2;
    // launch order puts attn_gemm at captured index 3
    qqk_kernel<<<dim3(T, B), 384>>>(x, qs_w, kv_w);                     // 0
    zero_out_kernel<<<512, 256>>>((float4*)d_out, h4);                  // 1
    zero_out_kernel<<<512, 256>>>((float4*)d_out + h4, n4 - h4);        // 2
    attn_gemm_kernel<<<dim3(NF/128, B), 128, GEMM_SMEM_BYTES>>>(x);     // 3
    topk_stage1_kernel<<<B*HT*2, 256>>>();                              // 4
    topk_merge_kernel<<<B*HT/4, 128>>>();                               // 5
    gather_scatter_kernel<<<dim3(T, H, B), 384>>>(x, experts_w, out);   // 6
    token_out_kernel<<<dim3(T, B), 384>>>(kv_w, experts_w, out);        // 7
}

// round 9
// speedup vs baseline: 1.2305x; 1.2305x over previous
#include <cuda_runtime.h>
#include <math.h>
#include <float.h>

#define B 4
#define T 8
#define NF 8192
#define C 384
#define H 12
#define TOPK 32
#define D 32
#define HT (H*T)        /* 96 */
#define ROWS (T+NF)     /* 8200 */
#define NH (NF/2)       /* 4096 per stage-1 half */
#define SCALE 0.17677669529663687f

typedef unsigned long long ull;
typedef unsigned int uint;

// ---------------- scratch (static device globals; no runtime alloc) ----------
__device__ float g_qk[B*HT*C];
__device__ float g_attn[(size_t)B*HT*NF];         // ~12.6MB
__device__ float g_w[B*HT*TOPK];
__device__ int   g_idx[B*HT*TOPK];
__device__ float g_fb[B*T*H*C];
__device__ ull   g_cand[B*HT][2][TOPK];           // stage-1 sorted candidates

// ---------------- helpers -----------------------------------------------------
__device__ __forceinline__ void red_add_v4(float* p, float4 v) {
    asm volatile("red.global.add.v4.f32 [%0], {%1, %2, %3, %4};"
                 :: "l"(p), "f"(v.x), "f"(v.y), "f"(v.z), "f"(v.w) : "memory");
}
__device__ __forceinline__ void mma_tf32(float* d,
                                         uint a0, uint a1, uint a2, uint a3,
                                         uint b0, uint b1) {
    asm("mma.sync.aligned.m16n8k8.row.col.f32.tf32.tf32.f32 "
        "{%0,%1,%2,%3}, {%4,%5,%6,%7}, {%8,%9}, {%0,%1,%2,%3};"
        : "+f"(d[0]), "+f"(d[1]), "+f"(d[2]), "+f"(d[3])
        : "r"(a0), "r"(a1), "r"(a2), "r"(a3), "r"(b0), "r"(b1));
}
__device__ __forceinline__ uint sptr(const void* p) {
    return (uint)__cvta_generic_to_shared(p);
}
__device__ __forceinline__ void cp16(uint dst, const float* src) {
    asm volatile("cp.async.cg.shared.global [%0], [%1], 16;" :: "r"(dst), "l"(src));
}
#define HIMASK 0xffffe000u

// ---------------- kernel 1: zero the output ----------------------------------
__global__ void zero_out_kernel(float4* __restrict__ out, int n4) {
    float4 z = make_float4(0.f, 0.f, 0.f, 0.f);
    for (int i = blockIdx.x * blockDim.x + threadIdx.x; i < n4;
         i += gridDim.x * blockDim.x)
        out[i] = z;
}

// ---------------- kernel 2: fused q projection + qk fold ---------------------
__global__ __launch_bounds__(384) void qqk_kernel(const float* __restrict__ x,
                                                  const float* __restrict__ qs_w,
                                                  const float* __restrict__ kv_w) {
    int b = blockIdx.y, t = blockIdx.x;
    int tid = threadIdx.x;                 // 384
    __shared__ float xs[C];
    __shared__ float qs[C];
    xs[tid] = x[((size_t)b*ROWS + t)*C + tid];
    __syncthreads();

    float a0 = 0.f, a1 = 0.f, a2 = 0.f, a3 = 0.f;
    const float* w = qs_w + (size_t)t*C*C + tid;
    #pragma unroll 4
    for (int c = 0; c < C; c += 4) {
        a0 += xs[c    ] * w[(size_t)(c    )*C];
        a1 += xs[c + 1] * w[(size_t)(c + 1)*C];
        a2 += xs[c + 2] * w[(size_t)(c + 2)*C];
        a3 += xs[c + 3] * w[(size_t)(c + 3)*C];
    }
    qs[tid] = (a0 + a1) + (a2 + a3);
    __syncthreads();

    const float4* kvr = (const float4*)(kv_w + (size_t)tid*(2*C));
    #pragma unroll
    for (int h = 0; h < H; h++) {
        float s = 0.f;
        #pragma unroll
        for (int d4 = 0; d4 < 8; d4++) {
            float4 kq = kvr[h*8 + d4];
            s += qs[h*D + 4*d4 + 0]*kq.x + qs[h*D + 4*d4 + 1]*kq.y
               + qs[h*D + 4*d4 + 2]*kq.z + qs[h*D + 4*d4 + 3]*kq.w;
        }
        g_qk[(((size_t)b*H + h)*T + t)*C + tid] = s * SCALE;
    }
}

// ---------------- kernel 3: attn GEMM, 3xTF32 mask-split, cp.async pipeline --
// Block 96x128, 256 threads = 8 warps (2m x 4n), warp tile 48x32, K-chunk 32.
// Raw f32 in smem (double-buffered, cp.async); Markidis split in registers.
// Stride 36: compute-phase bank = 4g + tig + 8*k8 -> all 32 distinct.
#define KSTRIDE 36
#define A_FL (96*KSTRIDE)
#define B_FL (128*KSTRIDE)
#define GEMM_SMEM_BYTES ((2*A_FL + 2*B_FL)*4)

__global__ __launch_bounds__(256, 2) void attn_gemm_kernel(const float* __restrict__ x) {
    extern __shared__ __align__(16) float smem_f[];
    float* sA0 = smem_f;
    float* sA1 = smem_f + A_FL;
    float* sB0 = smem_f + 2*A_FL;
    float* sB1 = smem_f + 2*A_FL + B_FL;

    int b  = blockIdx.y;
    int n0 = blockIdx.x * 128;
    int tid = threadIdx.x;
    int wid = tid >> 5, lane = tid & 31;
    int g = lane >> 2, tig = lane & 3;
    int wm = wid & 1, wn = wid >> 1;       // 2x4 warp grid

    const float* qk   = g_qk + (size_t)b*HT*C;
    const float* feat = x + ((size_t)b*ROWS + T)*C;

    // staging index precompute (7 x 16B cp.async per thread per chunk)
    int ar[3], ak[3], br[4], bk[4];
    #pragma unroll
    for (int j = 0; j < 3; j++) { int idx = tid + j*256; ar[j] = idx >> 3; ak[j] = (idx & 7)*4; }
    #pragma unroll
    for (int j = 0; j < 4; j++) { int idx = tid + j*256; br[j] = idx >> 3; bk[j] = (idx & 7)*4; }

    float acc[3][4][4];
    #pragma unroll
    for (int i = 0; i < 3; i++)
        #pragma unroll
        for (int j = 0; j < 4; j++)
            #pragma unroll
            for (int r = 0; r < 4; r++) acc[i][j][r] = 0.f;

    // issue chunk 0
    {
        #pragma unroll
        for (int j = 0; j < 3; j++)
            cp16(sptr(&sA0[ar[j]*KSTRIDE + ak[j]]), qk + (size_t)ar[j]*C + ak[j]);
        #pragma unroll
        for (int j = 0; j < 4; j++)
            cp16(sptr(&sB0[br[j]*KSTRIDE + bk[j]]), feat + (size_t)(n0 + br[j])*C + bk[j]);
        asm volatile("cp.async.commit_group;");
    }

    #pragma unroll 1
    for (int t = 0; t < 12; t++) {
        if (t < 11) {                      // issue chunk t+1 into the other buffer
            int c1 = (t + 1) * 32;
            float* dA = ((t + 1) & 1) ? sA1 : sA0;
            float* dB = ((t + 1) & 1) ? sB1 : sB0;
            #pragma unroll
            for (int j = 0; j < 3; j++)
                cp16(sptr(&dA[ar[j]*KSTRIDE + ak[j]]), qk + (size_t)ar[j]*C + c1 + ak[j]);
            #pragma unroll
            for (int j = 0; j < 4; j++)
                cp16(sptr(&dB[br[j]*KSTRIDE + bk[j]]), feat + (size_t)(n0 + br[j])*C + c1 + bk[j]);
            asm volatile("cp.async.commit_group;");
            asm volatile("cp.async.wait_group 1;");
        } else {
            asm volatile("cp.async.wait_group 0;");
        }
        __syncthreads();

        const float* cA = (t & 1) ? sA1 : sA0;
        const float* cB = (t & 1) ? sB1 : sB0;

        #pragma unroll
        for (int k8 = 0; k8 < 4; k8++) {
            int kc = k8*8 + tig;
            uint bh[4][2], bl[4][2];
            #pragma unroll
            for (int nt = 0; nt < 4; nt++) {
                int n = wn*32 + nt*8 + g;
                float b0 = cB[n*KSTRIDE + kc];
                float b1 = cB[n*KSTRIDE + kc + 4];
                uint u0 = __float_as_uint(b0) & HIMASK;
                uint u1 = __float_as_uint(b1) & HIMASK;
                bh[nt][0] = u0; bh[nt][1] = u1;
                bl[nt][0] = __float_as_uint(b0 - __uint_as_float(u0));
                bl[nt][1] = __float_as_uint(b1 - __uint_as_float(u1));
            }
            #pragma unroll
            for (int mt = 0; mt < 3; mt++) {
                int m0 = wm*48 + mt*16;
                float a0 = cA[(m0 + g    )*KSTRIDE + kc];
                float a1 = cA[(m0 + g + 8)*KSTRIDE + kc];
                float a2 = cA[(m0 + g    )*KSTRIDE + kc + 4];
                float a3 = cA[(m0 + g + 8)*KSTRIDE + kc + 4];
                uint ah0 = __float_as_uint(a0) & HIMASK;
                uint ah1 = __float_as_uint(a1) & HIMASK;
                uint ah2 = __float_as_uint(a2) & HIMASK;
                uint ah3 = __float_as_uint(a3) & HIMASK;
                uint al0 = __float_as_uint(a0 - __uint_as_float(ah0));
                uint al1 = __float_as_uint(a1 - __uint_as_float(ah1));
                uint al2 = __float_as_uint(a2 - __uint_as_float(ah2));
                uint al3 = __float_as_uint(a3 - __uint_as_float(ah3));
                #pragma unroll
                for (int nt = 0; nt < 4; nt++) {
                    float* d = acc[mt][nt];
                    mma_tf32(d, ah0, ah1, ah2, ah3, bh[nt][0], bh[nt][1]);
                    mma_tf32(d, ah0, ah1, ah2, ah3, bl[nt][0], bl[nt][1]);
                    mma_tf32(d, al0, al1, al2, al3, bh[nt][0], bh[nt][1]);
                }
            }
        }
        __syncthreads();
    }

    float* outp = g_attn + (size_t)b*HT*NF;
    #pragma unroll
    for (int mt = 0; mt < 3; mt++) {
        int m0 = wm*48 + mt*16;
        #pragma unroll
        for (int nt = 0; nt < 4; nt++) {
            int nc = n0 + wn*32 + nt*8 + 2*tig;
            *(float2*)&outp[(size_t)(m0 + g    )*NF + nc] =
                make_float2(acc[mt][nt][0], acc[mt][nt][1]);
            *(float2*)&outp[(size_t)(m0 + g + 8)*NF + nc] =
                make_float2(acc[mt][nt][2], acc[mt][nt][3]);
        }
    }
}

// ---------------- top-k stage 1: exact top-32 per 4096-half -------------------
__device__ __forceinline__ unsigned enc_key(unsigned b) {
    return (b & 0x80000000u) ? ~b : (b | 0x80000000u);
}
__device__ __forceinline__ float dec_key(unsigned u) {
    unsigned b = (u & 0x80000000u) ? (u ^ 0x80000000u) : ~u;
    return __uint_as_float(b);
}

__global__ __launch_bounds__(256) void topk_stage1_kernel() {
    int blk  = blockIdx.x;                 // row*2 + half
    int row  = blk >> 1;
    int half = blk & 1;
    int base = half * NH;
    int tid = threadIdx.x;                 // 256
    int lane = tid & 31, wp = tid >> 5;
    __shared__ unsigned keys[NH];          // 16KB
    __shared__ unsigned hist[256];
    __shared__ unsigned wsuf[8];
    __shared__ unsigned sh_need, sh_prefix;
    __shared__ int cntG;
    __shared__ unsigned candK[TOPK];
    __shared__ int candI[TOPK];
    __shared__ int ri[256];

    hist[tid] = 0;
    if (tid == 0) { sh_need = TOPK; sh_prefix = 0; cntG = 0; }
    __syncthreads();

    const uint4* src = (const uint4*)(g_attn + (size_t)row*NF + base);
    for (int i = tid; i < NH/4; i += 256) {
        uint4 u = src[i];
        unsigned k0 = enc_key(u.x), k1 = enc_key(u.y);
        unsigned k2 = enc_key(u.z), k3 = enc_key(u.w);
        keys[4*i+0] = k0; keys[4*i+1] = k1;
        keys[4*i+2] = k2; keys[4*i+3] = k3;
        atomicAdd(&hist[k0 >> 24], 1u);
        atomicAdd(&hist[k1 >> 24], 1u);
        atomicAdd(&hist[k2 >> 24], 1u);
        atomicAdd(&hist[k3 >> 24], 1u);
    }
    __syncthreads();

    #pragma unroll
    for (int pass = 0; pass < 4; pass++) {
        int shift = 24 - 8*pass;
        if (pass > 0) {
            hist[tid] = 0;
            __syncthreads();
            unsigned pref  = sh_prefix;
            unsigned pmask = 0xFFFFFFFFu << (shift + 8);
            for (int i = tid; i < NH; i += 256) {
                unsigned k = keys[i];
                if ((k & pmask) == pref) atomicAdd(&hist[(k >> shift) & 255], 1u);
            }
            __syncthreads();
        }

        unsigned v = hist[tid];
        unsigned inc = v;
        #pragma unroll
        for (int s = 1; s < 32; s <<= 1) {
            unsigned tv = __shfl_down_sync(0xffffffffu, inc, s);
            if (lane + s < 32) inc += tv;
        }
        if (lane == 0) wsuf[wp] = inc;
        __syncthreads();
        if (tid < 8) {
            unsigned tv = wsuf[tid];
            #pragma unroll
            for (int s = 1; s < 8; s <<= 1) {
                unsigned t2 = __shfl_down_sync(0xffu, tv, s);
                if (tid + s < 8) tv += t2;
            }
            wsuf[tid] = tv;
        }
        __syncthreads();
        unsigned incl = inc + (wp < 7 ? wsuf[wp + 1] : 0u);
        unsigned need = sh_need;
        unsigned excl = incl - v;
        if (incl >= need && excl < need) {
            sh_prefix = sh_prefix | ((unsigned)tid << shift);
            sh_need   = need - excl;
        }
        __syncthreads();
    }
    unsigned V = sh_prefix;
    int E = (int)sh_need;

    for (int i = tid; i < NH; i += 256) {
        unsigned k = keys[i];
        if (k > V) { int p = atomicAdd(&cntG, 1); candK[p] = k; candI[p] = base + i; }
    }
    __syncthreads();
    int G = cntG;

    int last = -1;
    for (int e = 0; e < E; e++) {
        int best = NH;
        for (int i = tid; i < NH; i += 256)
            if (keys[i] == V && i > last && i < best) best = i;
        ri[tid] = best;
        __syncthreads();
        for (int s = 128; s > 0; s >>= 1) {
            if (tid < s) ri[tid] = min(ri[tid], ri[tid + s]);
            __syncthreads();
        }
        int widx = ri[0];
        if (tid == 0) { candK[G + e] = V; candI[G + e] = base + widx; }
        last = widx;
        __syncthreads();
    }

    if (tid < 32) {
        unsigned k = candK[tid];
        int ix = candI[tid];
        ull ck = ((ull)k << 32) | (ull)(0xFFFFFFFFu - (unsigned)ix);
        int rank = 0;
        #pragma unroll
        for (int j = 0; j < 32; j++) {
            ull o = __shfl_sync(0xffffffffu, ck, j);
            rank += (o > ck);
        }
        g_cand[row][half][rank] = ck;
    }
}

// ---------------- top-k stage 2: merge halves + softmax -----------------------
__global__ __launch_bounds__(128) void topk_merge_kernel() {
    int row  = blockIdx.x * 4 + (threadIdx.x >> 5);
    int lane = threadIdx.x & 31;

    ull a = g_cand[row][0][lane];
    ull bq = g_cand[row][1][31 - lane];
    ull c = a > bq ? a : bq;

    #pragma unroll
    for (int st = 16; st > 0; st >>= 1) {
        ull o = __shfl_xor_sync(0xffffffffu, c, st);
        bool up = (lane & st) == 0;
        c = up ? (c > o ? c : o) : (c < o ? c : o);
    }

    float val = dec_key((unsigned)(c >> 32));
    int   idx = (int)(0xFFFFFFFFu - (unsigned)(c & 0xFFFFFFFFu));

    float m = __shfl_sync(0xffffffffu, val, 0);
    float e = expf(val - m);
    float sum = e;
    #pragma unroll
    for (int o = 16; o > 0; o >>= 1) sum += __shfl_xor_sync(0xffffffffu, sum, o);

    g_w[row*TOPK + lane]   = e / sum;
    g_idx[row*TOPK + lane] = idx;
}

// ---------------- kernel 5: fused gather (fb) + vectorized sparse scatter ----
__global__ __launch_bounds__(384) void gather_scatter_kernel(const float* __restrict__ x,
                                                             const float* __restrict__ experts_w,
                                                             float* __restrict__ out) {
    int t = blockIdx.x, h = blockIdx.y, b = blockIdx.z;
    int tid = threadIdx.x;                 // 384
    __shared__ float wsh[TOPK];
    __shared__ int   ish[TOPK];
    __shared__ float fsh[TOPK][D];
    __shared__ __align__(16) float sc[4][C];

    int row = (b*H + h)*T + t;
    if (tid < TOPK) {
        wsh[tid] = g_w[row*TOPK + tid];
        ish[tid] = g_idx[row*TOPK + tid];
    }
    __syncthreads();

    const float* feat = x + ((size_t)b*ROWS + T)*C;
    int c = tid;
    int hD = h*D;
    bool mine = (c >= hD) && (c < hD + D);
    int d = c - hD;
    float a = 0.f;
    #pragma unroll
    for (int k = 0; k < TOPK; k++) {
        float v  = feat[(size_t)ish[k]*C + c];
        float wv = wsh[k] * v;
        a += wv;
        if (mine) fsh[k][d] = wv;
    }
    g_fb[(((size_t)b*T + t)*H + h)*C + c] = a;
    __syncthreads();

    int o = tid;
    float ecol[D];
    const float* ew = experts_w + ((size_t)t*C + hD)*C + o;
    #pragma unroll
    for (int d2 = 0; d2 < D; d2++) ecol[d2] = ew[(size_t)d2*C];

    float* outb = out + ((size_t)b*ROWS + T)*C;
    int kq = tid / (C/4);
    int o4 = tid % (C/4);
    #pragma unroll 1
    for (int gI = 0; gI < TOPK/4; gI++) {
        #pragma unroll
        for (int j = 0; j < 4; j++) {
            int k = gI*4 + j;
            float s = 0.f;
            #pragma unroll
            for (int d2 = 0; d2 < D; d2++) s += fsh[k][d2] * ecol[d2];
            sc[j][o] = s;
        }
        __syncthreads();
        float4 v = *(const float4*)&sc[kq][4*o4];
        red_add_v4(&outb[(size_t)ish[gI*4 + kq]*C + 4*o4], v);
        __syncthreads();
    }
}

// ---------------- kernel 6: attn_token projection + token_out ----------------
__global__ __launch_bounds__(384) void token_out_kernel(const float* __restrict__ kv_w,
                                                        const float* __restrict__ experts_w,
                                                        float* __restrict__ out) {
    int b = blockIdx.y, t = blockIdx.x;
    int tid = threadIdx.x;                 // 384
    __shared__ float fb[H*C];              // 18KB
    __shared__ float at[C];

    const float* fbg = g_fb + ((size_t)b*T + t)*H*C;
    for (int i = tid; i < H*C; i += 384) fb[i] = fbg[i];
    __syncthreads();

    {
        int h = tid >> 5, d = tid & 31;
        const float* col = kv_w + C + h*D + d;
        float a0 = 0.f, a1 = 0.f, a2 = 0.f, a3 = 0.f;
        #pragma unroll 2
        for (int c = 0; c < C; c += 4) {
            a0 += fb[h*C + c    ] * col[(size_t)(c    )*(2*C)];
            a1 += fb[h*C + c + 1] * col[(size_t)(c + 1)*(2*C)];
            a2 += fb[h*C + c + 2] * col[(size_t)(c + 2)*(2*C)];
            a3 += fb[h*C + c + 3] * col[(size_t)(c + 3)*(2*C)];
        }
        at[h*D + d] = (a0 + a1) + (a2 + a3);
    }
    __syncthreads();
    {
        const float* ew = experts_w + (size_t)t*C*C + tid;
        float a0 = 0.f, a1 = 0.f, a2 = 0.f, a3 = 0.f;
        #pragma unroll 2
        for (int c = 0; c < C; c += 4) {
            a0 += at[c    ] * ew[(size_t)(c    )*C];
            a1 += at[c + 1] * ew[(size_t)(c + 1)*C];
            a2 += at[c + 2] * ew[(size_t)(c + 2)*C];
            a3 += at[c + 3] * ew[(size_t)(c + 3)*C];
        }
        out[((size_t)b*ROWS + t)*C + tid] = (a0 + a1) + (a2 + a3);
    }
}

// ---------------- launcher ----------------------------------------------------
extern "C" void kernel_launch(void* const* d_in, const int* in_sizes, int n_in,
                              void* d_out, int out_size) {
    const float* x = nullptr; const float* qs_w = nullptr;
    const float* kv_w = nullptr; const float* experts_w = nullptr;
    for (int i = 0; i < n_in; i++) {
        if (in_sizes[i] == B*ROWS*C)      x = (const float*)d_in[i];
        else if (in_sizes[i] == C*2*C)    kv_w = (const float*)d_in[i];
        else if (in_sizes[i] == T*C*C) {
            if (!qs_w) qs_w = (const float*)d_in[i];
            else       experts_w = (const float*)d_in[i];
        }
    }
    float* out = (float*)d_out;

    cudaFuncSetAttribute(attn_gemm_kernel,
                         cudaFuncAttributeMaxDynamicSharedMemorySize,
                         (int)GEMM_SMEM_BYTES);

    int n4 = out_size / 4;
    int h4 = n4 / 2;
    // launch order keeps attn_gemm at captured index 3
    qqk_kernel<<<dim3(T, B), 384>>>(x, qs_w, kv_w);                     // 0
    zero_out_kernel<<<512, 256>>>((float4*)d_out, h4);                  // 1
    zero_out_kernel<<<512, 256>>>((float4*)d_out + h4, n4 - h4);        // 2
    attn_gemm_kernel<<<dim3(NF/128, B), 256, GEMM_SMEM_BYTES>>>(x);     // 3
    topk_stage1_kernel<<<B*HT*2, 256>>>();                              // 4
    topk_merge_kernel<<<B*HT/4, 128>>>();                               // 5
    gather_scatter_kernel<<<dim3(T, H, B), 384>>>(x, experts_w, out);   // 6
    token_out_kernel<<<dim3(T, B), 384>>>(kv_w, experts_w, out);        // 7
}

// round 10
// speedup vs baseline: 2.0954x; 1.7029x over previous
#include <cuda_runtime.h>
#include <math.h>
#include <float.h>

#define B 4
#define T 8
#define NF 8192
#define C 384
#define H 12
#define TOPK 32
#define D 32
#define HT (H*T)        /* 96 */
#define ROWS (T+NF)     /* 8200 */
#define NH (NF/2)       /* 4096 per stage-1 half */
#define SCALE 0.17677669529663687f

typedef unsigned long long ull;
typedef unsigned int uint;

// ---------------- scratch (static device globals; no runtime alloc) ----------
__device__ float g_q[B*T*C];                      // 48KB
__device__ float g_at[B*T*C];                     // 48KB
__device__ float g_qk[B*HT*C];
__device__ float g_attn[(size_t)B*HT*NF];         // ~12.6MB
__device__ float g_w[B*HT*TOPK];
__device__ int   g_idx[B*HT*TOPK];
__device__ ull   g_cand[B*HT][2][TOPK];           // stage-1 sorted candidates

// ---------------- helpers -----------------------------------------------------
__device__ __forceinline__ void red_add_v4(float* p, float4 v) {
    asm volatile("red.global.add.v4.f32 [%0], {%1, %2, %3, %4};"
                 :: "l"(p), "f"(v.x), "f"(v.y), "f"(v.z), "f"(v.w) : "memory");
}
__device__ __forceinline__ void mma_tf32(float* d,
                                         uint a0, uint a1, uint a2, uint a3,
                                         uint b0, uint b1) {
    asm("mma.sync.aligned.m16n8k8.row.col.f32.tf32.tf32.f32 "
        "{%0,%1,%2,%3}, {%4,%5,%6,%7}, {%8,%9}, {%0,%1,%2,%3};"
        : "+f"(d[0]), "+f"(d[1]), "+f"(d[2]), "+f"(d[3])
        : "r"(a0), "r"(a1), "r"(a2), "r"(a3), "r"(b0), "r"(b1));
}
__device__ __forceinline__ uint sptr(const void* p) {
    return (uint)__cvta_generic_to_shared(p);
}
__device__ __forceinline__ void cp16(uint dst, const float* src) {
    asm volatile("cp.async.cg.shared.global [%0], [%1], 16;" :: "r"(dst), "l"(src));
}
#define HIMASK 0xffffe000u

// ---------------- kernel: zero scratch accumulators ---------------------------
__global__ void zero_scratch_kernel() {
    int i = blockIdx.x * blockDim.x + threadIdx.x;
    if (i < B*T*C) { g_q[i] = 0.f; g_at[i] = 0.f; }
}

// ---------------- kernel: zero the output -------------------------------------
__global__ void zero_out_kernel(float4* __restrict__ out, int n4) {
    float4 z = make_float4(0.f, 0.f, 0.f, 0.f);
    for (int i = blockIdx.x * blockDim.x + threadIdx.x; i < n4;
         i += gridDim.x * blockDim.x)
        out[i] = z;
}

// ---------------- kernel: q projection, c-split with atomic reduction ---------
// q[b,t,o] = sum_c x[b,t,c]*qs_w[t,c,o]; grid (8 csplit, T), 384 thr (=o)
__global__ __launch_bounds__(384) void q_kernel(const float* __restrict__ x,
                                                const float* __restrict__ qs_w) {
    int cs = blockIdx.x, t = blockIdx.y;
    int tid = threadIdx.x;
    __shared__ float xs[4][48];
    if (tid < 192) {
        int b = tid / 48, c = tid % 48;
        xs[b][c] = x[((size_t)b*ROWS + t)*C + cs*48 + c];
    }
    __syncthreads();
    float a0 = 0.f, a1 = 0.f, a2 = 0.f, a3 = 0.f;
    const float* w = qs_w + (size_t)t*C*C + (size_t)cs*48*C + tid;
    #pragma unroll 4
    for (int c = 0; c < 48; c++) {
        float wv = w[(size_t)c*C];
        a0 += xs[0][c]*wv; a1 += xs[1][c]*wv;
        a2 += xs[2][c]*wv; a3 += xs[3][c]*wv;
    }
    atomicAdd(&g_q[(0*T + t)*C + tid], a0);
    atomicAdd(&g_q[(1*T + t)*C + tid], a1);
    atomicAdd(&g_q[(2*T + t)*C + tid], a2);
    atomicAdd(&g_q[(3*T + t)*C + tid], a3);
}

// ---------------- kernel: qk fold, 96 blocks x 4 kv rows ----------------------
// qk[b,h,t,c] = SCALE * sum_d q[b,t,hD+d]*kv_w[c, hD+d]
#define QPAD 392
#define QK_SMEM_BYTES ((32*QPAD + 4*QPAD)*4)
__global__ __launch_bounds__(384) void qk_kernel(const float* __restrict__ kv_w) {
    extern __shared__ float qsm[];
    float* qs  = qsm;                      // [32][QPAD]  (b*8+t rows)
    float* kvs = qsm + 32*QPAD;            // [4][QPAD]

    int c0 = blockIdx.x * 4;
    int tid = threadIdx.x;
    int h = tid >> 5, t = (tid >> 2) & 7, cl = tid & 3;

    #pragma unroll
    for (int r = 0; r < 32; r++) qs[r*QPAD + tid] = g_q[r*C + tid];
    #pragma unroll
    for (int r = 0; r < 4; r++)
        kvs[r*QPAD + tid] = kv_w[(size_t)(c0 + r)*(2*C) + tid];
    __syncthreads();

    const float* krow = &kvs[cl*QPAD + h*D];
    #pragma unroll
    for (int b = 0; b < 4; b++) {
        const float* qrow = &qs[(b*8 + t)*QPAD + h*D];
        float s = 0.f;
        #pragma unroll
        for (int d = 0; d < D; d++) s += qrow[d] * krow[d];
        g_qk[(((size_t)b*H + h)*T + t)*C + c0 + cl] = s * SCALE;
    }
}

// ---------------- kernel: attn GEMM (FROZEN: 49.4us, tensor 54.5%) -----------
#define KSTRIDE 36
#define A_FL (96*KSTRIDE)
#define B_FL (128*KSTRIDE)
#define GEMM_SMEM_BYTES ((2*A_FL + 2*B_FL)*4)

__global__ __launch_bounds__(256, 2) void attn_gemm_kernel(const float* __restrict__ x) {
    extern __shared__ __align__(16) float smem_f[];
    float* sA0 = smem_f;
    float* sA1 = smem_f + A_FL;
    float* sB0 = smem_f + 2*A_FL;
    float* sB1 = smem_f + 2*A_FL + B_FL;

    int b  = blockIdx.y;
    int n0 = blockIdx.x * 128;
    int tid = threadIdx.x;
    int wid = tid >> 5, lane = tid & 31;
    int g = lane >> 2, tig = lane & 3;
    int wm = wid & 1, wn = wid >> 1;

    const float* qk   = g_qk + (size_t)b*HT*C;
    const float* feat = x + ((size_t)b*ROWS + T)*C;

    int ar[3], ak[3], br[4], bk[4];
    #pragma unroll
    for (int j = 0; j < 3; j++) { int idx = tid + j*256; ar[j] = idx >> 3; ak[j] = (idx & 7)*4; }
    #pragma unroll
    for (int j = 0; j < 4; j++) { int idx = tid + j*256; br[j] = idx >> 3; bk[j] = (idx & 7)*4; }

    float acc[3][4][4];
    #pragma unroll
    for (int i = 0; i < 3; i++)
        #pragma unroll
        for (int j = 0; j < 4; j++)
            #pragma unroll
            for (int r = 0; r < 4; r++) acc[i][j][r] = 0.f;

    {
        #pragma unroll
        for (int j = 0; j < 3; j++)
            cp16(sptr(&sA0[ar[j]*KSTRIDE + ak[j]]), qk + (size_t)ar[j]*C + ak[j]);
        #pragma unroll
        for (int j = 0; j < 4; j++)
            cp16(sptr(&sB0[br[j]*KSTRIDE + bk[j]]), feat + (size_t)(n0 + br[j])*C + bk[j]);
        asm volatile("cp.async.commit_group;");
    }

    #pragma unroll 1
    for (int t = 0; t < 12; t++) {
        if (t < 11) {
            int c1 = (t + 1) * 32;
            float* dA = ((t + 1) & 1) ? sA1 : sA0;
            float* dB = ((t + 1) & 1) ? sB1 : sB0;
            #pragma unroll
            for (int j = 0; j < 3; j++)
                cp16(sptr(&dA[ar[j]*KSTRIDE + ak[j]]), qk + (size_t)ar[j]*C + c1 + ak[j]);
            #pragma unroll
            for (int j = 0; j < 4; j++)
                cp16(sptr(&dB[br[j]*KSTRIDE + bk[j]]), feat + (size_t)(n0 + br[j])*C + c1 + bk[j]);
            asm volatile("cp.async.commit_group;");
            asm volatile("cp.async.wait_group 1;");
        } else {
            asm volatile("cp.async.wait_group 0;");
        }
        __syncthreads();

        const float* cA = (t & 1) ? sA1 : sA0;
        const float* cB = (t & 1) ? sB1 : sB0;

        #pragma unroll
        for (int k8 = 0; k8 < 4; k8++) {
            int kc = k8*8 + tig;
            uint bh[4][2], bl[4][2];
            #pragma unroll
            for (int nt = 0; nt < 4; nt++) {
                int n = wn*32 + nt*8 + g;
                float b0 = cB[n*KSTRIDE + kc];
                float b1 = cB[n*KSTRIDE + kc + 4];
                uint u0 = __float_as_uint(b0) & HIMASK;
                uint u1 = __float_as_uint(b1) & HIMASK;
                bh[nt][0] = u0; bh[nt][1] = u1;
                bl[nt][0] = __float_as_uint(b0 - __uint_as_float(u0));
                bl[nt][1] = __float_as_uint(b1 - __uint_as_float(u1));
            }
            #pragma unroll
            for (int mt = 0; mt < 3; mt++) {
                int m0 = wm*48 + mt*16;
                float a0 = cA[(m0 + g    )*KSTRIDE + kc];
                float a1 = cA[(m0 + g + 8)*KSTRIDE + kc];
                float a2 = cA[(m0 + g    )*KSTRIDE + kc + 4];
                float a3 = cA[(m0 + g + 8)*KSTRIDE + kc + 4];
                uint ah0 = __float_as_uint(a0) & HIMASK;
                uint ah1 = __float_as_uint(a1) & HIMASK;
                uint ah2 = __float_as_uint(a2) & HIMASK;
                uint ah3 = __float_as_uint(a3) & HIMASK;
                uint al0 = __float_as_uint(a0 - __uint_as_float(ah0));
                uint al1 = __float_as_uint(a1 - __uint_as_float(ah1));
                uint al2 = __float_as_uint(a2 - __uint_as_float(ah2));
                uint al3 = __float_as_uint(a3 - __uint_as_float(ah3));
                #pragma unroll
                for (int nt = 0; nt < 4; nt++) {
                    float* d = acc[mt][nt];
                    mma_tf32(d, ah0, ah1, ah2, ah3, bh[nt][0], bh[nt][1]);
                    mma_tf32(d, ah0, ah1, ah2, ah3, bl[nt][0], bl[nt][1]);
                    mma_tf32(d, al0, al1, al2, al3, bh[nt][0], bh[nt][1]);
                }
            }
        }
        __syncthreads();
    }

    float* outp = g_attn + (size_t)b*HT*NF;
    #pragma unroll
    for (int mt = 0; mt < 3; mt++) {
        int m0 = wm*48 + mt*16;
        #pragma unroll
        for (int nt = 0; nt < 4; nt++) {
            int nc = n0 + wn*32 + nt*8 + 2*tig;
            *(float2*)&outp[(size_t)(m0 + g    )*NF + nc] =
                make_float2(acc[mt][nt][0], acc[mt][nt][1]);
            *(float2*)&outp[(size_t)(m0 + g + 8)*NF + nc] =
                make_float2(acc[mt][nt][2], acc[mt][nt][3]);
        }
    }
}

// ---------------- top-k stage 1 (FROZEN) --------------------------------------
__device__ __forceinline__ unsigned enc_key(unsigned b) {
    return (b & 0x80000000u) ? ~b : (b | 0x80000000u);
}
__device__ __forceinline__ float dec_key(unsigned u) {
    unsigned b = (u & 0x80000000u) ? (u ^ 0x80000000u) : ~u;
    return __uint_as_float(b);
}

__global__ __launch_bounds__(256) void topk_stage1_kernel() {
    int blk  = blockIdx.x;
    int row  = blk >> 1;
    int half = blk & 1;
    int base = half * NH;
    int tid = threadIdx.x;
    int lane = tid & 31, wp = tid >> 5;
    __shared__ unsigned keys[NH];
    __shared__ unsigned hist[256];
    __shared__ unsigned wsuf[8];
    __shared__ unsigned sh_need, sh_prefix;
    __shared__ int cntG;
    __shared__ unsigned candK[TOPK];
    __shared__ int candI[TOPK];
    __shared__ int ri[256];

    hist[tid] = 0;
    if (tid == 0) { sh_need = TOPK; sh_prefix = 0; cntG = 0; }
    __syncthreads();

    const uint4* src = (const uint4*)(g_attn + (size_t)row*NF + base);
    for (int i = tid; i < NH/4; i += 256) {
        uint4 u = src[i];
        unsigned k0 = enc_key(u.x), k1 = enc_key(u.y);
        unsigned k2 = enc_key(u.z), k3 = enc_key(u.w);
        keys[4*i+0] = k0; keys[4*i+1] = k1;
        keys[4*i+2] = k2; keys[4*i+3] = k3;
        atomicAdd(&hist[k0 >> 24], 1u);
        atomicAdd(&hist[k1 >> 24], 1u);
        atomicAdd(&hist[k2 >> 24], 1u);
        atomicAdd(&hist[k3 >> 24], 1u);
    }
    __syncthreads();

    #pragma unroll
    for (int pass = 0; pass < 4; pass++) {
        int shift = 24 - 8*pass;
        if (pass > 0) {
            hist[tid] = 0;
            __syncthreads();
            unsigned pref  = sh_prefix;
            unsigned pmask = 0xFFFFFFFFu << (shift + 8);
            for (int i = tid; i < NH; i += 256) {
                unsigned k = keys[i];
                if ((k & pmask) == pref) atomicAdd(&hist[(k >> shift) & 255], 1u);
            }
            __syncthreads();
        }

        unsigned v = hist[tid];
        unsigned inc = v;
        #pragma unroll
        for (int s = 1; s < 32; s <<= 1) {
            unsigned tv = __shfl_down_sync(0xffffffffu, inc, s);
            if (lane + s < 32) inc += tv;
        }
        if (lane == 0) wsuf[wp] = inc;
        __syncthreads();
        if (tid < 8) {
            unsigned tv = wsuf[tid];
            #pragma unroll
            for (int s = 1; s < 8; s <<= 1) {
                unsigned t2 = __shfl_down_sync(0xffu, tv, s);
                if (tid + s < 8) tv += t2;
            }
            wsuf[tid] = tv;
        }
        __syncthreads();
        unsigned incl = inc + (wp < 7 ? wsuf[wp + 1] : 0u);
        unsigned need = sh_need;
        unsigned excl = incl - v;
        if (incl >= need && excl < need) {
            sh_prefix = sh_prefix | ((unsigned)tid << shift);
            sh_need   = need - excl;
        }
        __syncthreads();
    }
    unsigned V = sh_prefix;
    int E = (int)sh_need;

    for (int i = tid; i < NH; i += 256) {
        unsigned k = keys[i];
        if (k > V) { int p = atomicAdd(&cntG, 1); candK[p] = k; candI[p] = base + i; }
    }
    __syncthreads();
    int G = cntG;

    int last = -1;
    for (int e = 0; e < E; e++) {
        int best = NH;
        for (int i = tid; i < NH; i += 256)
            if (keys[i] == V && i > last && i < best) best = i;
        ri[tid] = best;
        __syncthreads();
        for (int s = 128; s > 0; s >>= 1) {
            if (tid < s) ri[tid] = min(ri[tid], ri[tid + s]);
            __syncthreads();
        }
        int widx = ri[0];
        if (tid == 0) { candK[G + e] = V; candI[G + e] = base + widx; }
        last = widx;
        __syncthreads();
    }

    if (tid < 32) {
        unsigned k = candK[tid];
        int ix = candI[tid];
        ull ck = ((ull)k << 32) | (ull)(0xFFFFFFFFu - (unsigned)ix);
        int rank = 0;
        #pragma unroll
        for (int j = 0; j < 32; j++) {
            ull o = __shfl_sync(0xffffffffu, ck, j);
            rank += (o > ck);
        }
        g_cand[row][half][rank] = ck;
    }
}

// ---------------- top-k stage 2: merge + softmax (FROZEN) ---------------------
__global__ __launch_bounds__(128) void topk_merge_kernel() {
    int row  = blockIdx.x * 4 + (threadIdx.x >> 5);
    int lane = threadIdx.x & 31;

    ull a = g_cand[row][0][lane];
    ull bq = g_cand[row][1][31 - lane];
    ull c = a > bq ? a : bq;

    #pragma unroll
    for (int st = 16; st > 0; st >>= 1) {
        ull o = __shfl_xor_sync(0xffffffffu, c, st);
        bool up = (lane & st) == 0;
        c = up ? (c > o ? c : o) : (c < o ? c : o);
    }

    float val = dec_key((unsigned)(c >> 32));
    int   idx = (int)(0xFFFFFFFFu - (unsigned)(c & 0xFFFFFFFFu));

    float m = __shfl_sync(0xffffffffu, val, 0);
    float e = expf(val - m);
    float sum = e;
    #pragma unroll
    for (int o = 16; o > 0; o >>= 1) sum += __shfl_xor_sync(0xffffffffu, sum, o);

    g_w[row*TOPK + lane]   = e / sum;
    g_idx[row*TOPK + lane] = idx;
}

// ---------------- kernel: gather + at-projection + sparse scatter -------------
// fb[c] = sum_k w*feature[idx,c]; at[b,t,hD+d] += sum_c fb[c]*kv_w[c, C+hD+d];
// out[b,T+idx,:] += fsh[k,:] @ experts_w[t, hD:, :]
__global__ __launch_bounds__(384) void gather_scatter_kernel(const float* __restrict__ x,
                                                             const float* __restrict__ kv_w,
                                                             const float* __restrict__ experts_w,
                                                             float* __restrict__ out) {
    int t = blockIdx.x, h = blockIdx.y, b = blockIdx.z;
    int tid = threadIdx.x;                 // 384
    __shared__ float wsh[TOPK];
    __shared__ int   ish[TOPK];
    __shared__ float fsh[TOPK][D];
    __shared__ float fbs[C];
    __shared__ __align__(16) float sc[4][C];

    int row = (b*H + h)*T + t;
    if (tid < TOPK) {
        wsh[tid] = g_w[row*TOPK + tid];
        ish[tid] = g_idx[row*TOPK + tid];
    }
    __syncthreads();

    const float* feat = x + ((size_t)b*ROWS + T)*C;
    int c = tid;
    int hD = h*D;
    bool mine = (c >= hD) && (c < hD + D);
    int d = c - hD;
    float a = 0.f;
    #pragma unroll
    for (int k = 0; k < TOPK; k++) {
        float v  = feat[(size_t)ish[k]*C + c];
        float wv = wsh[k] * v;
        a += wv;
        if (mine) fsh[k][d] = wv;
    }
    fbs[c] = a;
    __syncthreads();

    // at-projection: o = hD+dd, partial over 32 c-rows per cs-group
    {
        int dd = tid & 31, cs = tid >> 5;  // cs 0..11
        float part = 0.f;
        const float* kvv = kv_w + C + hD + dd;
        #pragma unroll 4
        for (int c2 = 0; c2 < 32; c2++) {
            int cc = cs*32 + c2;
            part += fbs[cc] * kvv[(size_t)cc*(2*C)];
        }
        atomicAdd(&g_at[((size_t)b*T + t)*C + hD + dd], part);
    }

    // sparse scatter
    int o = tid;
    float ecol[D];
    const float* ew = experts_w + ((size_t)t*C + hD)*C + o;
    #pragma unroll
    for (int d2 = 0; d2 < D; d2++) ecol[d2] = ew[(size_t)d2*C];

    float* outb = out + ((size_t)b*ROWS + T)*C;
    int kq = tid / (C/4);
    int o4 = tid % (C/4);
    #pragma unroll 1
    for (int gI = 0; gI < TOPK/4; gI++) {
        #pragma unroll
        for (int j = 0; j < 4; j++) {
            int k = gI*4 + j;
            float s = 0.f;
            #pragma unroll
            for (int d2 = 0; d2 < D; d2++) s += fsh[k][d2] * ecol[d2];
            sc[j][o] = s;
        }
        __syncthreads();
        float4 v = *(const float4*)&sc[kq][4*o4];
        red_add_v4(&outb[(size_t)ish[gI*4 + kq]*C + 4*o4], v);
        __syncthreads();
    }
}

// ---------------- kernel: token_out = at @ experts_w, c-split -----------------
__global__ __launch_bounds__(384) void token_final_kernel(const float* __restrict__ experts_w,
                                                          float* __restrict__ out) {
    int cs = blockIdx.x, t = blockIdx.y;
    int tid = threadIdx.x;
    __shared__ float ats[4][48];
    if (tid < 192) {
        int b = tid / 48, c = tid % 48;
        ats[b][c] = g_at[((size_t)b*T + t)*C + cs*48 + c];
    }
    __syncthreads();
    float a0 = 0.f, a1 = 0.f, a2 = 0.f, a3 = 0.f;
    const float* w = experts_w + (size_t)t*C*C + (size_t)cs*48*C + tid;
    #pragma unroll 4
    for (int c = 0; c < 48; c++) {
        float wv = w[(size_t)c*C];
        a0 += ats[0][c]*wv; a1 += ats[1][c]*wv;
        a2 += ats[2][c]*wv; a3 += ats[3][c]*wv;
    }
    atomicAdd(&out[((size_t)0*ROWS + t)*C + tid], a0);
    atomicAdd(&out[((size_t)1*ROWS + t)*C + tid], a1);
    atomicAdd(&out[((size_t)2*ROWS + t)*C + tid], a2);
    atomicAdd(&out[((size_t)3*ROWS + t)*C + tid], a3);
}

// ---------------- launcher ----------------------------------------------------
extern "C" void kernel_launch(void* const* d_in, const int* in_sizes, int n_in,
                              void* d_out, int out_size) {
    const float* x = nullptr; const float* qs_w = nullptr;
    const float* kv_w = nullptr; const float* experts_w = nullptr;
    for (int i = 0; i < n_in; i++) {
        if (in_sizes[i] == B*ROWS*C)      x = (const float*)d_in[i];
        else if (in_sizes[i] == C*2*C)    kv_w = (const float*)d_in[i];
        else if (in_sizes[i] == T*C*C) {
            if (!qs_w) qs_w = (const float*)d_in[i];
            else       experts_w = (const float*)d_in[i];
        }
    }
    float* out = (float*)d_out;

    cudaFuncSetAttribute(attn_gemm_kernel,
                         cudaFuncAttributeMaxDynamicSharedMemorySize,
                         (int)GEMM_SMEM_BYTES);
    cudaFuncSetAttribute(qk_kernel,
                         cudaFuncAttributeMaxDynamicSharedMemorySize,
                         (int)QK_SMEM_BYTES);

    zero_scratch_kernel<<<48, 256>>>();                                  // 0
    zero_out_kernel<<<1024, 256>>>((float4*)d_out, out_size / 4);        // 1
    q_kernel<<<dim3(8, T), 384>>>(x, qs_w);                              // 2
    qk_kernel<<<96, 384, QK_SMEM_BYTES>>>(kv_w);                         // 3
    attn_gemm_kernel<<<dim3(NF/128, B), 256, GEMM_SMEM_BYTES>>>(x);      // 4
    topk_stage1_kernel<<<B*HT*2, 256>>>();                               // 5
    topk_merge_kernel<<<B*HT/4, 128>>>();                                // 6
    gather_scatter_kernel<<<dim3(T, H, B), 384>>>(x, kv_w, experts_w, out); // 7
    token_final_kernel<<<dim3(8, T), 384>>>(experts_w, out);             // 8
}